// round 12
// baseline (speedup 1.0000x reference)
#include <cuda_runtime.h>
#include <cstdint>
#include <math.h>

typedef unsigned long long ull;

#define NTH 1024
#define VP 72          // padded v/r row pitch (floats)
#define VR 36          // v rows per CTA: 32 own + 2 halo each side
#define RROWS 36
#define MROWS 40
#define MP 68

// shared-memory layout (float offsets)
#define OFF_VA 0
#define OFF_VB 2592
#define OFF_R  5184
#define OFF_M  7776                    // ints, 40*68 = 2720
#define OFF_WQ 10496                   // wqT[25][8]
#define OFF_WW 10696                   // wwT[25][8]
#define OFF_FC 10896                   // fcT[8][4]
#define OFF_LT 10928                   // LUT[25][4]
#define OFF_WE 11028                   // Weff[2][25] (+pad)
#define OFF_BE 11080
#define OFF_QR 11088                   // qr chan-pair planes: ull[4][32][64]
#define SM_FLOATS (OFF_QR + 8*32*64)   // 27472
#define SMEM_BYTES (SM_FLOATS * 4)     // 109888 B

#define FMA2(d,a,b,c) asm("fma.rn.f32x2 %0,%1,%2,%3;" : "=l"(d) : "l"(a), "l"(b), "l"(c))
#define PACK2(d,lo,hi) asm("mov.b64 %0,{%1,%2};" : "=l"(d) : "f"(lo), "f"(hi))
#define UNPK2(lo,hi,s) asm("mov.b64 {%0,%1},%2;" : "=f"(lo), "=f"(hi) : "l"(s))

__device__ __forceinline__ uint32_t smem_u32(const void* p) {
    uint32_t a;
    asm("{ .reg .u64 t; cvta.to.shared.u64 t, %1; cvt.u32.u64 %0, t; }"
        : "=r"(a) : "l"(p));
    return a;
}
__device__ __forceinline__ uint32_t mapa_rank(uint32_t a, uint32_t rk) {
    uint32_t r;
    asm("mapa.shared::cluster.u32 %0, %1, %2;" : "=r"(r) : "r"(a), "r"(rk));
    return r;
}
__device__ __forceinline__ void st_remote_f2(uint32_t a, float x, float y) {
    asm volatile("st.shared::cluster.v2.f32 [%0], {%1,%2};"
                 :: "r"(a), "f"(x), "f"(y) : "memory");
}
#define CSYNC() do { \
    asm volatile("barrier.cluster.arrive.aligned;" ::: "memory"); \
    asm volatile("barrier.cluster.wait.aligned;"   ::: "memory"); } while (0)

// Load one padded-plane row (6 cols from (yo+r_, x0)) and splat into ull pairs.
#define LOAD_SROW(s_, base_, r_) do {                                     \
    const float* rp_ = (base_) + (yo + (r_)) * VP + x0;                   \
    float2 p0_ = *(const float2*)(rp_);                                   \
    float2 p1_ = *(const float2*)(rp_ + 2);                               \
    float2 p2_ = *(const float2*)(rp_ + 4);                               \
    PACK2(s_[0], p0_.x, p0_.x); PACK2(s_[1], p0_.y, p0_.y);               \
    PACK2(s_[2], p1_.x, p1_.x); PACK2(s_[3], p1_.y, p1_.y);               \
    PACK2(s_[4], p2_.x, p2_.x); PACK2(s_[5], p2_.y, p2_.y);               \
} while (0)

// 5x5 conv, one output row, 2 cols, channel-paired accumulators qc2[4][2].
#define CONV_PAIRS(vplane_)                                               \
    _Pragma("unroll")                                                     \
    for (int ky = 0; ky < 5; ky++) {                                      \
        ull s_[6];                                                        \
        LOAD_SROW(s_, vplane_, ky);                                       \
        _Pragma("unroll")                                                 \
        for (int kx = 0; kx < 5; kx++) {                                  \
            const ulonglong2* wp_ = (const ulonglong2*)(wT + (ky*5 + kx)*8); \
            ulonglong2 wA_ = wp_[0], wB_ = wp_[1];                        \
            FMA2(qc2[0][0], wA_.x, s_[kx],   qc2[0][0]);                  \
            FMA2(qc2[0][1], wA_.x, s_[kx+1], qc2[0][1]);                  \
            FMA2(qc2[1][0], wA_.y, s_[kx],   qc2[1][0]);                  \
            FMA2(qc2[1][1], wA_.y, s_[kx+1], qc2[1][1]);                  \
            FMA2(qc2[2][0], wB_.x, s_[kx],   qc2[2][0]);                  \
            FMA2(qc2[2][1], wB_.x, s_[kx+1], qc2[2][1]);                  \
            FMA2(qc2[3][0], wB_.y, s_[kx],   qc2[3][0]);                  \
            FMA2(qc2[3][1], wB_.y, s_[kx+1], qc2[3][1]);                  \
        }                                                                 \
    }

__global__ void __cluster_dims__(2,1,1) __launch_bounds__(NTH, 1)
vin_kernel(const int*   __restrict__ maze,
           const float* __restrict__ emb,
           const float* __restrict__ encode_w,
           const float* __restrict__ encode_b,
           const float* __restrict__ r_w,
           const float* __restrict__ q_w,
           const float* __restrict__ w,
           const float* __restrict__ fc_w,
           float* __restrict__ out)
{
    extern __shared__ float sm[];
    float* rsm = sm + OFF_R;
    int*   msm = (int*)(sm + OFF_M);
    float* wqT = sm + OFF_WQ;
    float* wwT = sm + OFF_WW;
    float* fcT = sm + OFF_FC;
    float* Lt  = sm + OFF_LT;
    float* We  = sm + OFF_WE;
    ull*   qru = (ull*)(sm + OFF_QR);   // [cp][32][64] channel-pair planes

    const int tid  = threadIdx.x;
    const int rank = blockIdx.x;        // 0 = rows 0..31, 1 = rows 32..63
    const int b    = blockIdx.y;
    const int tx   = tid & 31;
    const int ty   = tid >> 5;          // 0..31: one row per thread
    const int x0   = tx * 2;
    const int yo   = ty;
    const int gy0  = rank * 32;

    const uint32_t my32   = smem_u32(sm);
    const uint32_t peer32 = mapa_rank(my32, rank ^ 1);

    // halo-exchange role for this thread (1 row each)
    const bool sendlo = (rank == 0) & (ty >= 30);   // rows 30,31 -> peer rows 0,1
    const bool sendhi = (rank == 1) & (ty <= 1);    // rows 0,1  -> peer rows 34,35
    const int  peer_row = sendlo ? (ty - 30) : (34 + ty);

    // ---------------- prologue ----------------
    for (int i = tid; i < 200; i += NTH) {
        int c = i / 25, t = i - c * 25;
        wqT[t * 8 + c] = q_w[i];
        wwT[t * 8 + c] = w[i];
    }
    if (tid < 32) { int a = tid >> 3, c = tid & 7; fcT[c * 4 + a] = fc_w[tid]; }
    if (tid >= 64 && tid < 114) {
        int t = tid - 64;
        float s = 0.f;
        #pragma unroll 5
        for (int c = 0; c < 150; ++c) s += r_w[c] * encode_w[c * 50 + t];
        We[t] = s;
    }
    if (tid == 63) {
        float s = 0.f;
        for (int c = 0; c < 150; ++c) s += r_w[c] * encode_b[c];
        sm[OFF_BE] = s;
    }
    for (int i = tid; i < MROWS * MP; i += NTH) msm[i] = 3;  // sentinel
    for (int i = tid; i < VR * VP; i += NTH) {
        sm[OFF_VA + i] = 0.f; sm[OFF_VB + i] = 0.f; rsm[i] = 0.f;
    }
    __syncthreads();

    if (tid < 75) {
        int t = tid / 3, mv = tid - t * 3;
        Lt[t * 4 + mv] = We[t] * emb[2 * mv] + We[25 + t] * emb[2 * mv + 1];
        if (mv == 0) Lt[t * 4 + 3] = 0.f;
    }
    const int* mz = maze + b * 4096;
    for (int i = tid; i < MROWS * 64; i += NTH) {
        int mr = i >> 6, c = i & 63, g = gy0 - 4 + mr;
        if ((unsigned)g < 64u) msm[mr * MP + c + 2] = mz[g * 64 + c];
    }
    CSYNC();   // local: LUT/maze visible; cluster: peer's v buffers zeroed

    // ---------------- r = LUT-conv(maze) + b_eff ----------------
    {
        const float bv = sm[OFF_BE];
        for (int i = tid; i < RROWS * 64; i += NTH) {
            int vr = i >> 6, c = i & 63, g = gy0 - 2 + vr;
            if ((unsigned)g < 64u) {
                float s = bv;
                #pragma unroll
                for (int dy = 0; dy < 5; dy++)
                    #pragma unroll
                    for (int dx = 0; dx < 5; dx++)
                        s += Lt[(dy * 5 + dx) * 4 + msm[(vr + dy) * MP + c + dx]];
                rsm[vr * VP + c + 2] = s;
            }
        }
    }
    __syncthreads();

    // ---------------- qr = conv(r, wq); v0 = max_c qr ----------------
    {
        ull qc2[4][2];
        #pragma unroll
        for (int cp = 0; cp < 4; cp++) { qc2[cp][0] = 0ull; qc2[cp][1] = 0ull; }
        const float* wT = wqT;
        CONV_PAIRS(rsm);
        // store qr + compute v0
        float vn[2];
        #pragma unroll
        for (int cp = 0; cp < 4; cp++) {
            ulonglong2 st; st.x = qc2[cp][0]; st.y = qc2[cp][1];
            *(ulonglong2*)(qru + cp * 2048 + yo * 64 + x0) = st;
        }
        #pragma unroll
        for (int j = 0; j < 2; j++) {
            float lo, hi;
            UNPK2(lo, hi, qc2[0][j]);
            float m = fmaxf(lo, hi);
            #pragma unroll
            for (int cp = 1; cp < 4; cp++) {
                UNPK2(lo, hi, qc2[cp][j]);
                m = fmaxf(m, fmaxf(lo, hi));
            }
            vn[j] = m;
        }
        *(float2*)(sm + OFF_VA + (yo + 2) * VP + x0 + 2) = make_float2(vn[0], vn[1]);
        if (sendlo | sendhi)
            st_remote_f2(peer32 + (OFF_VA + peer_row * VP + x0 + 2) * 4, vn[0], vn[1]);
    }
    CSYNC();

    // ---------------- 9 value-iteration steps ----------------
    for (int k = 0; k < 9; ++k) {
        const int inOff  = (k & 1) ? OFF_VB : OFF_VA;
        const int outOff = (k & 1) ? OFF_VA : OFF_VB;
        const float* vin = sm + inOff;
        ull qc2[4][2];
        #pragma unroll
        for (int cp = 0; cp < 4; cp++) {
            ulonglong2 ld = *(const ulonglong2*)(qru + cp * 2048 + yo * 64 + x0);
            qc2[cp][0] = ld.x; qc2[cp][1] = ld.y;
        }
        const float* wT = wwT;
        CONV_PAIRS(vin);
        float vn[2];
        #pragma unroll
        for (int j = 0; j < 2; j++) {
            float lo, hi;
            UNPK2(lo, hi, qc2[0][j]);
            float m = fmaxf(lo, hi);
            #pragma unroll
            for (int cp = 1; cp < 4; cp++) {
                UNPK2(lo, hi, qc2[cp][j]);
                m = fmaxf(m, fmaxf(lo, hi));
            }
            vn[j] = m;
        }
        *(float2*)(sm + outOff + (yo + 2) * VP + x0 + 2) = make_float2(vn[0], vn[1]);
        if (sendlo | sendhi)
            st_remote_f2(peer32 + (outOff + peer_row * VP + x0 + 2) * 4, vn[0], vn[1]);
        CSYNC();
    }

    // ---------------- final: q10 = qr + conv(v9,w); out = q10 @ fc^T ----------------
    {
        const float* vin = sm + OFF_VB;   // v9 in buffer B
        ull qc2[4][2];
        #pragma unroll
        for (int cp = 0; cp < 4; cp++) {
            ulonglong2 ld = *(const ulonglong2*)(qru + cp * 2048 + yo * 64 + x0);
            qc2[cp][0] = ld.x; qc2[cp][1] = ld.y;
        }
        const float* wT = wwT;
        CONV_PAIRS(vin);
        float* og = out + (size_t)b * 4096 * 4;
        #pragma unroll
        for (int j = 0; j < 2; j++) {
            float q[8];
            #pragma unroll
            for (int cp = 0; cp < 4; cp++)
                UNPK2(q[2 * cp], q[2 * cp + 1], qc2[cp][j]);
            float4 o = make_float4(0.f, 0.f, 0.f, 0.f);
            #pragma unroll
            for (int c = 0; c < 8; c++) {
                float4 fr = *(const float4*)(fcT + c * 4);
                o.x += q[c] * fr.x;
                o.y += q[c] * fr.y;
                o.z += q[c] * fr.z;
                o.w += q[c] * fr.w;
            }
            *(float4*)(og + ((gy0 + yo) * 64 + x0 + j) * 4) = o;
        }
    }
}

extern "C" void kernel_launch(void* const* d_in, const int* in_sizes, int n_in,
                              void* d_out, int out_size) {
    cudaFuncSetAttribute(vin_kernel, cudaFuncAttributeMaxDynamicSharedMemorySize,
                         SMEM_BYTES);
    const int B = in_sizes[0] >> 12;   // maze elements / 4096
    dim3 grid(2, B, 1);
    vin_kernel<<<grid, NTH, SMEM_BYTES>>>(
        (const int*)  d_in[0],  // maze
        (const float*)d_in[1],  // emb
        (const float*)d_in[2],  // encode_w
        (const float*)d_in[3],  // encode_b
        (const float*)d_in[4],  // r_w
        (const float*)d_in[5],  // q_w
        (const float*)d_in[6],  // w
        (const float*)d_in[7],  // fc_w
        (float*)d_out);
}

// round 14
// speedup vs baseline: 1.0594x; 1.0594x over previous
#include <cuda_runtime.h>
#include <cstdint>
#include <math.h>

typedef unsigned long long ull;

#define NTH 512
#define UPITCH 72       // splat-plane row pitch in ull
#define MROWS 40
#define MP 68

// shared-memory layout (float offsets). Splat planes are ull[36][72].
#define OFF_VA 0                        // 5184 floats
#define OFF_VB 5184                     // 5184 floats
#define OFF_R  10368                    // 5184 floats (splat r)
#define OFF_M  15552                    // ints, 40*68 = 2720
#define OFF_WQ 18272                    // wqT[25][8]
#define OFF_WW 18472                    // wwT[25][8]
#define OFF_FC 18672                    // fcT[8][4]
#define OFF_LT 18704                    // LUT[25][4]
#define OFF_WE 18804                    // Weff[2][25] (+pad)
#define OFF_BE 18856
#define SM_FLOATS 18860
#define SMEM_BYTES (SM_FLOATS * 4)      // 75440 B

#define FMA2(d,a,b,c) asm("fma.rn.f32x2 %0,%1,%2,%3;" : "=l"(d) : "l"(a), "l"(b), "l"(c))
#define PACK2(d,lo,hi) asm("mov.b64 %0,{%1,%2};" : "=l"(d) : "f"(lo), "f"(hi))
#define UNPK2(lo,hi,s) asm("mov.b64 {%0,%1},%2;" : "=f"(lo), "=f"(hi) : "l"(s))

__device__ __forceinline__ uint32_t smem_u32(const void* p) {
    uint32_t a;
    asm("{ .reg .u64 t; cvta.to.shared.u64 t, %1; cvt.u32.u64 %0, t; }"
        : "=r"(a) : "l"(p));
    return a;
}
__device__ __forceinline__ uint32_t mapa_rank(uint32_t a, uint32_t rk) {
    uint32_t r;
    asm("mapa.shared::cluster.u32 %0, %1, %2;" : "=r"(r) : "r"(a), "r"(rk));
    return r;
}
__device__ __forceinline__ void st_remote_f4(uint32_t a, float x, float y,
                                             float z, float w_) {
    asm volatile("st.shared::cluster.v4.f32 [%0], {%1,%2,%3,%4};"
                 :: "r"(a), "f"(x), "f"(y), "f"(z), "f"(w_) : "memory");
}
#define CSYNC() do { \
    asm volatile("barrier.cluster.arrive.aligned;" ::: "memory"); \
    asm volatile("barrier.cluster.wait.aligned;"   ::: "memory"); } while (0)

// Load 6 splat operands (cols x0..x0+5 of splat plane row yo+r_) via 3 LDS.128.
#define LOAD_SROW(s_, plane_, r_) do {                                        \
    const ulonglong2* rp_ =                                                   \
        (const ulonglong2*)((plane_) + (yo + (r_)) * UPITCH + x0);            \
    ulonglong2 a_ = rp_[0], b_ = rp_[1], c_ = rp_[2];                         \
    s_[0] = a_.x; s_[1] = a_.y; s_[2] = b_.x;                                 \
    s_[3] = b_.y; s_[4] = c_.x; s_[5] = c_.y;                                 \
} while (0)

// One tap-row sweep: rA_ feeds output row i=0, rB_ row i=1. 16 FMA2 per kx.
#define KY_STEP(ky_, rA_, rB_)                                                \
    _Pragma("unroll")                                                         \
    for (int kx = 0; kx < 5; kx++) {                                          \
        const ulonglong2* wp_ = (const ulonglong2*)(wT + ((ky_)*5 + kx)*8);   \
        ulonglong2 wA_ = wp_[0], wB_ = wp_[1];                                \
        FMA2(qc2[0][0][0], wA_.x, rA_[kx],   qc2[0][0][0]);                   \
        FMA2(qc2[0][0][1], wA_.x, rA_[kx+1], qc2[0][0][1]);                   \
        FMA2(qc2[0][1][0], wA_.x, rB_[kx],   qc2[0][1][0]);                   \
        FMA2(qc2[0][1][1], wA_.x, rB_[kx+1], qc2[0][1][1]);                   \
        FMA2(qc2[1][0][0], wA_.y, rA_[kx],   qc2[1][0][0]);                   \
        FMA2(qc2[1][0][1], wA_.y, rA_[kx+1], qc2[1][0][1]);                   \
        FMA2(qc2[1][1][0], wA_.y, rB_[kx],   qc2[1][1][0]);                   \
        FMA2(qc2[1][1][1], wA_.y, rB_[kx+1], qc2[1][1][1]);                   \
        FMA2(qc2[2][0][0], wB_.x, rA_[kx],   qc2[2][0][0]);                   \
        FMA2(qc2[2][0][1], wB_.x, rA_[kx+1], qc2[2][0][1]);                   \
        FMA2(qc2[2][1][0], wB_.x, rB_[kx],   qc2[2][1][0]);                   \
        FMA2(qc2[2][1][1], wB_.x, rB_[kx+1], qc2[2][1][1]);                   \
        FMA2(qc2[3][0][0], wB_.y, rA_[kx],   qc2[3][0][0]);                   \
        FMA2(qc2[3][0][1], wB_.y, rA_[kx+1], qc2[3][0][1]);                   \
        FMA2(qc2[3][1][0], wB_.y, rB_[kx],   qc2[3][1][0]);                   \
        FMA2(qc2[3][1][1], wB_.y, rB_[kx+1], qc2[3][1][1]);                   \
    }

// Full 5x5 conv, rolling 2-row splat ring, accumulating into qc2[4][2][2].
#define CONV_PAIRS(uplane_)                                                   \
    do {                                                                      \
        ull s0[6], s1[6];                                                     \
        LOAD_SROW(s0, uplane_, 0);                                            \
        LOAD_SROW(s1, uplane_, 1);                                            \
        KY_STEP(0, s0, s1)                                                    \
        LOAD_SROW(s0, uplane_, 2);                                            \
        KY_STEP(1, s1, s0)                                                    \
        LOAD_SROW(s1, uplane_, 3);                                            \
        KY_STEP(2, s0, s1)                                                    \
        LOAD_SROW(s0, uplane_, 4);                                            \
        KY_STEP(3, s1, s0)                                                    \
        LOAD_SROW(s1, uplane_, 5);                                            \
        KY_STEP(4, s0, s1)                                                    \
    } while (0)

__global__ void __cluster_dims__(2,1,1) __launch_bounds__(NTH, 1)
vin_kernel(const int*   __restrict__ maze,
           const float* __restrict__ emb,
           const float* __restrict__ encode_w,
           const float* __restrict__ encode_b,
           const float* __restrict__ r_w,
           const float* __restrict__ q_w,
           const float* __restrict__ w,
           const float* __restrict__ fc_w,
           float* __restrict__ out)
{
    extern __shared__ float sm[];
    ull*   vaU = (ull*)(sm + OFF_VA);
    ull*   vbU = (ull*)(sm + OFF_VB);
    ull*   rU  = (ull*)(sm + OFF_R);
    int*   msm = (int*)(sm + OFF_M);
    float* wqT = sm + OFF_WQ;
    float* wwT = sm + OFF_WW;
    float* fcT = sm + OFF_FC;
    float* Lt  = sm + OFF_LT;
    float* We  = sm + OFF_WE;

    const int tid  = threadIdx.x;
    const int rank = blockIdx.x;        // 0 = rows 0..31, 1 = rows 32..63
    const int b    = blockIdx.y;
    const int tx   = tid & 31;
    const int ty   = tid >> 5;          // 0..15
    const int x0   = tx * 2;
    const int yo   = ty * 2;            // 2 rows per thread
    const int gy0  = rank * 32;

    const uint32_t my32   = smem_u32(sm);
    const uint32_t peer32 = mapa_rank(my32, rank ^ 1);

    // halo roles: rank0 ty==15 sends rows 30,31 -> peer rows 0,1
    //             rank1 ty==0  sends rows 0,1   -> peer rows 34,35
    const bool sendlo = (rank == 0) & (ty == 15);
    const bool sendhi = (rank == 1) & (ty == 0);
    const int  prow0  = sendlo ? 0 : 34;    // peer halo row for local row yo

    // ---------------- prologue ----------------
    for (int i = tid; i < 200; i += NTH) {
        int c = i / 25, t = i - c * 25;
        wqT[t * 8 + c] = q_w[i];
        wwT[t * 8 + c] = w[i];
    }
    if (tid < 32) { int a = tid >> 3, c = tid & 7; fcT[c * 4 + a] = fc_w[tid]; }
    if (tid >= 64 && tid < 114) {
        int t = tid - 64;
        float s = 0.f;
        #pragma unroll 5
        for (int c = 0; c < 150; ++c) s += r_w[c] * encode_w[c * 50 + t];
        We[t] = s;
    }
    if (tid == 63) {
        float s = 0.f;
        for (int c = 0; c < 150; ++c) s += r_w[c] * encode_b[c];
        sm[OFF_BE] = s;
    }
    for (int i = tid; i < MROWS * MP; i += NTH) msm[i] = 3;  // sentinel
    for (int i = tid; i < OFF_M; i += NTH) sm[i] = 0.f;      // VA, VB, R splat planes
    __syncthreads();

    if (tid < 75) {
        int t = tid / 3, mv = tid - t * 3;
        Lt[t * 4 + mv] = We[t] * emb[2 * mv] + We[25 + t] * emb[2 * mv + 1];
        if (mv == 0) Lt[t * 4 + 3] = 0.f;
    }
    const int* mz = maze + b * 4096;
    for (int i = tid; i < MROWS * 64; i += NTH) {
        int mr = i >> 6, c = i & 63, g = gy0 - 4 + mr;
        if ((unsigned)g < 64u) msm[mr * MP + c + 2] = mz[g * 64 + c];
    }
    CSYNC();   // local: LUT/maze visible; cluster: peer's v planes zeroed

    // ---------------- r = LUT-conv(maze) + b_eff (splat-stored) ----------------
    {
        const float bv = sm[OFF_BE];
        for (int i = tid; i < 36 * 64; i += NTH) {
            int vr = i >> 6, c = i & 63, g = gy0 - 2 + vr;
            if ((unsigned)g < 64u) {
                float s = bv;
                #pragma unroll
                for (int dy = 0; dy < 5; dy++)
                    #pragma unroll
                    for (int dx = 0; dx < 5; dx++)
                        s += Lt[(dy * 5 + dx) * 4 + msm[(vr + dy) * MP + c + dx]];
                ull sp; PACK2(sp, s, s);
                rU[vr * UPITCH + c + 2] = sp;
            }
        }
    }
    __syncthreads();

    // ---------------- qr = conv(r, wq) -> REGISTERS; v0 = max_c qr ----------------
    ull qr2[4][2][2];
    {
        ull qc2[4][2][2];
        #pragma unroll
        for (int cp = 0; cp < 4; cp++)
            #pragma unroll
            for (int i = 0; i < 2; i++) { qc2[cp][i][0] = 0ull; qc2[cp][i][1] = 0ull; }
        const float* wT = wqT;
        CONV_PAIRS(rU);
        #pragma unroll
        for (int cp = 0; cp < 4; cp++)
            #pragma unroll
            for (int i = 0; i < 2; i++) {
                qr2[cp][i][0] = qc2[cp][i][0];
                qr2[cp][i][1] = qc2[cp][i][1];
            }
        // v0 = max over channels
        float vn[2][2];
        #pragma unroll
        for (int i = 0; i < 2; i++)
            #pragma unroll
            for (int j = 0; j < 2; j++) {
                float lo, hi;
                UNPK2(lo, hi, qc2[0][i][j]);
                float m = fmaxf(lo, hi);
                #pragma unroll
                for (int cp = 1; cp < 4; cp++) {
                    UNPK2(lo, hi, qc2[cp][i][j]);
                    m = fmaxf(m, fmaxf(lo, hi));
                }
                vn[i][j] = m;
            }
        #pragma unroll
        for (int i = 0; i < 2; i++) {
            ulonglong2 st;
            PACK2(st.x, vn[i][0], vn[i][0]);
            PACK2(st.y, vn[i][1], vn[i][1]);
            *(ulonglong2*)(vaU + (yo + 2 + i) * UPITCH + x0 + 2) = st;
        }
        if (sendlo | sendhi) {
            #pragma unroll
            for (int i = 0; i < 2; i++)
                st_remote_f4(peer32 + OFF_VA * 4 +
                                 ((prow0 + i) * UPITCH + x0 + 2) * 8,
                             vn[i][0], vn[i][0], vn[i][1], vn[i][1]);
        }
    }
    CSYNC();

    // ---------------- 9 value-iteration steps ----------------
    for (int k = 0; k < 9; ++k) {
        const ull* vin  = (k & 1) ? vbU : vaU;
        ull*       vout = (k & 1) ? vaU : vbU;
        const int  outOffB = ((k & 1) ? OFF_VA : OFF_VB) * 4;
        ull qc2[4][2][2];
        #pragma unroll
        for (int cp = 0; cp < 4; cp++)
            #pragma unroll
            for (int i = 0; i < 2; i++) {
                qc2[cp][i][0] = qr2[cp][i][0];
                qc2[cp][i][1] = qr2[cp][i][1];
            }
        const float* wT = wwT;
        CONV_PAIRS(vin);
        float vn[2][2];
        #pragma unroll
        for (int i = 0; i < 2; i++)
            #pragma unroll
            for (int j = 0; j < 2; j++) {
                float lo, hi;
                UNPK2(lo, hi, qc2[0][i][j]);
                float m = fmaxf(lo, hi);
                #pragma unroll
                for (int cp = 1; cp < 4; cp++) {
                    UNPK2(lo, hi, qc2[cp][i][j]);
                    m = fmaxf(m, fmaxf(lo, hi));
                }
                vn[i][j] = m;
            }
        #pragma unroll
        for (int i = 0; i < 2; i++) {
            ulonglong2 st;
            PACK2(st.x, vn[i][0], vn[i][0]);
            PACK2(st.y, vn[i][1], vn[i][1]);
            *(ulonglong2*)(vout + (yo + 2 + i) * UPITCH + x0 + 2) = st;
        }
        if (sendlo | sendhi) {
            #pragma unroll
            for (int i = 0; i < 2; i++)
                st_remote_f4(peer32 + outOffB +
                                 ((prow0 + i) * UPITCH + x0 + 2) * 8,
                             vn[i][0], vn[i][0], vn[i][1], vn[i][1]);
        }
        CSYNC();
    }

    // ---------------- final: q10 = qr + conv(v9,w); out = q10 @ fc^T ----------------
    {
        const ull* vin = vbU;   // v9 in plane B (k=8 even wrote B)
        ull qc2[4][2][2];
        #pragma unroll
        for (int cp = 0; cp < 4; cp++)
            #pragma unroll
            for (int i = 0; i < 2; i++) {
                qc2[cp][i][0] = qr2[cp][i][0];
                qc2[cp][i][1] = qr2[cp][i][1];
            }
        const float* wT = wwT;
        CONV_PAIRS(vin);
        float* og = out + (size_t)b * 4096 * 4;
        #pragma unroll
        for (int i = 0; i < 2; i++)
            #pragma unroll
            for (int j = 0; j < 2; j++) {
                float q[8];
                #pragma unroll
                for (int cp = 0; cp < 4; cp++)
                    UNPK2(q[2 * cp], q[2 * cp + 1], qc2[cp][i][j]);
                float4 o = make_float4(0.f, 0.f, 0.f, 0.f);
                #pragma unroll
                for (int c = 0; c < 8; c++) {
                    float4 fr = *(const float4*)(fcT + c * 4);
                    o.x += q[c] * fr.x;
                    o.y += q[c] * fr.y;
                    o.z += q[c] * fr.z;
                    o.w += q[c] * fr.w;
                }
                *(float4*)(og + ((gy0 + yo + i) * 64 + x0 + j) * 4) = o;
            }
    }
}

extern "C" void kernel_launch(void* const* d_in, const int* in_sizes, int n_in,
                              void* d_out, int out_size) {
    cudaFuncSetAttribute(vin_kernel, cudaFuncAttributeMaxDynamicSharedMemorySize,
                         SMEM_BYTES);
    const int B = in_sizes[0] >> 12;   // maze elements / 4096
    dim3 grid(2, B, 1);
    vin_kernel<<<grid, NTH, SMEM_BYTES>>>(
        (const int*)  d_in[0],  // maze
        (const float*)d_in[1],  // emb
        (const float*)d_in[2],  // encode_w
        (const float*)d_in[3],  // encode_b
        (const float*)d_in[4],  // r_w
        (const float*)d_in[5],  // q_w
        (const float*)d_in[6],  // w
        (const float*)d_in[7],  // fc_w
        (float*)d_out);
}

// round 16
// speedup vs baseline: 1.2209x; 1.1524x over previous
#include <cuda_runtime.h>
#include <cstdint>
#include <math.h>

typedef unsigned long long ull;

#define NTH 512
#define VP 72           // padded v/r row pitch (floats)
#define MROWS 40
#define MP 68

// shared-memory layout (float offsets)
#define OFF_VA 0                       // 36*72 = 2592
#define OFF_VB 2592
#define OFF_R  5184
#define OFF_M  7776                    // ints, 40*68 = 2720
#define OFF_WQ 10496                   // wqT[25][8]
#define OFF_WW 10696                   // wwT[25][8]
#define OFF_FC 10896                   // fcT[8][4]
#define OFF_LT 10928                   // LUT[25][4]
#define OFF_WE 11028                   // Weff[2][25] (+pad)
#define OFF_BE 11080
#define OFF_MBAR 11082                 // 8-byte mbarrier (11082*4 % 8 == 0)
#define SM_FLOATS 11084
#define SMEM_BYTES (SM_FLOATS * 4)     // 44336 B

#define FMA2(d,a,b,c) asm("fma.rn.f32x2 %0,%1,%2,%3;" : "=l"(d) : "l"(a), "l"(b), "l"(c))
#define PACK2(d,lo,hi) asm("mov.b64 %0,{%1,%2};" : "=l"(d) : "f"(lo), "f"(hi))
#define UNPK2(lo,hi,s) asm("mov.b64 {%0,%1},%2;" : "=f"(lo), "=f"(hi) : "l"(s))

__device__ __forceinline__ uint32_t smem_u32(const void* p) {
    uint32_t a;
    asm("{ .reg .u64 t; cvta.to.shared.u64 t, %1; cvt.u32.u64 %0, t; }"
        : "=r"(a) : "l"(p));
    return a;
}
__device__ __forceinline__ uint32_t mapa_rank(uint32_t a, uint32_t rk) {
    uint32_t r;
    asm("mapa.shared::cluster.u32 %0, %1, %2;" : "=r"(r) : "r"(a), "r"(rk));
    return r;
}
__device__ __forceinline__ void st_remote_f2(uint32_t a, float x, float y) {
    asm volatile("st.shared::cluster.v2.f32 [%0], {%1,%2};"
                 :: "r"(a), "f"(x), "f"(y) : "memory");
}
__device__ __forceinline__ void mbar_init(uint32_t a, uint32_t cnt) {
    asm volatile("mbarrier.init.shared.b64 [%0], %1;" :: "r"(a), "r"(cnt) : "memory");
}
__device__ __forceinline__ void mbar_arrive_remote(uint32_t a) {
    asm volatile("mbarrier.arrive.shared::cluster.b64 _, [%0];" :: "r"(a) : "memory");
}
__device__ __forceinline__ void mbar_wait(uint32_t a, uint32_t par) {
    asm volatile(
        "{\n\t.reg .pred P;\n\t"
        "W%=:\n\t"
        "mbarrier.try_wait.parity.acquire.cluster.shared::cta.b64 P, [%0], %1, 0x989680;\n\t"
        "@P bra D%=;\n\t"
        "bra W%=;\n\t"
        "D%=:\n\t}"
        :: "r"(a), "r"(par) : "memory");
}
#define CSYNC() do { \
    asm volatile("barrier.cluster.arrive.aligned;" ::: "memory"); \
    asm volatile("barrier.cluster.wait.aligned;"   ::: "memory"); } while (0)

// Load 6 window floats (cols x0..x0+5 at plane row yo+r_) and splat to ull pairs.
#define LOAD_SROW(s_, base_, r_) do {                                     \
    const float* rp_ = (base_) + (yo + (r_)) * VP + x0;                   \
    float2 p0_ = *(const float2*)(rp_);                                   \
    float2 p1_ = *(const float2*)(rp_ + 2);                               \
    float2 p2_ = *(const float2*)(rp_ + 4);                               \
    PACK2(s_[0], p0_.x, p0_.x); PACK2(s_[1], p0_.y, p0_.y);               \
    PACK2(s_[2], p1_.x, p1_.x); PACK2(s_[3], p1_.y, p1_.y);               \
    PACK2(s_[4], p2_.x, p2_.x); PACK2(s_[5], p2_.y, p2_.y);               \
} while (0)

// One tap-row sweep: rA_ feeds output row i=0, rB_ row i=1. 16 FMA2 per kx.
#define KY_STEP(ky_, rA_, rB_)                                                \
    _Pragma("unroll")                                                         \
    for (int kx = 0; kx < 5; kx++) {                                          \
        const ulonglong2* wp_ = (const ulonglong2*)(wT + ((ky_)*5 + kx)*8);   \
        ulonglong2 wA_ = wp_[0], wB_ = wp_[1];                                \
        FMA2(qc2[0][0][0], wA_.x, rA_[kx],   qc2[0][0][0]);                   \
        FMA2(qc2[0][0][1], wA_.x, rA_[kx+1], qc2[0][0][1]);                   \
        FMA2(qc2[0][1][0], wA_.x, rB_[kx],   qc2[0][1][0]);                   \
        FMA2(qc2[0][1][1], wA_.x, rB_[kx+1], qc2[0][1][1]);                   \
        FMA2(qc2[1][0][0], wA_.y, rA_[kx],   qc2[1][0][0]);                   \
        FMA2(qc2[1][0][1], wA_.y, rA_[kx+1], qc2[1][0][1]);                   \
        FMA2(qc2[1][1][0], wA_.y, rB_[kx],   qc2[1][1][0]);                   \
        FMA2(qc2[1][1][1], wA_.y, rB_[kx+1], qc2[1][1][1]);                   \
        FMA2(qc2[2][0][0], wB_.x, rA_[kx],   qc2[2][0][0]);                   \
        FMA2(qc2[2][0][1], wB_.x, rA_[kx+1], qc2[2][0][1]);                   \
        FMA2(qc2[2][1][0], wB_.x, rB_[kx],   qc2[2][1][0]);                   \
        FMA2(qc2[2][1][1], wB_.x, rB_[kx+1], qc2[2][1][1]);                   \
        FMA2(qc2[3][0][0], wB_.y, rA_[kx],   qc2[3][0][0]);                   \
        FMA2(qc2[3][0][1], wB_.y, rA_[kx+1], qc2[3][0][1]);                   \
        FMA2(qc2[3][1][0], wB_.y, rB_[kx],   qc2[3][1][0]);                   \
        FMA2(qc2[3][1][1], wB_.y, rB_[kx+1], qc2[3][1][1]);                   \
    }

// Full 5x5 conv, rolling 2-row splat ring, accumulating into qc2[4][2][2].
#define CONV_PAIRS(fplane_)                                                   \
    do {                                                                      \
        ull s0[6], s1[6];                                                     \
        LOAD_SROW(s0, fplane_, 0);                                            \
        LOAD_SROW(s1, fplane_, 1);                                            \
        KY_STEP(0, s0, s1)                                                    \
        LOAD_SROW(s0, fplane_, 2);                                            \
        KY_STEP(1, s1, s0)                                                    \
        LOAD_SROW(s1, fplane_, 3);                                            \
        KY_STEP(2, s0, s1)                                                    \
        LOAD_SROW(s0, fplane_, 4);                                            \
        KY_STEP(3, s1, s0)                                                    \
        LOAD_SROW(s1, fplane_, 5);                                            \
        KY_STEP(4, s0, s1)                                                    \
    } while (0)

__global__ void __cluster_dims__(2,1,1) __launch_bounds__(NTH, 1)
vin_kernel(const int*   __restrict__ maze,
           const float* __restrict__ emb,
           const float* __restrict__ encode_w,
           const float* __restrict__ encode_b,
           const float* __restrict__ r_w,
           const float* __restrict__ q_w,
           const float* __restrict__ w,
           const float* __restrict__ fc_w,
           float* __restrict__ out)
{
    extern __shared__ float sm[];
    float* vaF = sm + OFF_VA;
    float* vbF = sm + OFF_VB;
    float* rF  = sm + OFF_R;
    int*   msm = (int*)(sm + OFF_M);
    float* wqT = sm + OFF_WQ;
    float* wwT = sm + OFF_WW;
    float* fcT = sm + OFF_FC;
    float* Lt  = sm + OFF_LT;
    float* We  = sm + OFF_WE;

    const int tid  = threadIdx.x;
    const int rank = blockIdx.x;        // 0 = rows 0..31, 1 = rows 32..63
    const int b    = blockIdx.y;
    const int tx   = tid & 31;
    const int ty   = tid >> 5;          // 0..15
    const int x0   = tx * 2;
    const int yo   = ty * 2;            // 2 rows per thread
    const int gy0  = rank * 32;

    const uint32_t my32   = smem_u32(sm);
    const uint32_t peer32 = mapa_rank(my32, rank ^ 1);
    const uint32_t mbarL  = my32   + OFF_MBAR * 4;
    const uint32_t mbarR  = peer32 + OFF_MBAR * 4;

    // boundary warps: rank0/ty15 sends rows 30,31 -> peer plane rows 0,1;
    //                 rank1/ty0  sends rows 0,1   -> peer plane rows 34,35.
    const bool sendlo = (rank == 0) & (ty == 15);
    const bool sendhi = (rank == 1) & (ty == 0);
    const bool bwarp  = sendlo | sendhi;
    const int  prow0  = sendlo ? 0 : 34;

    // ---------------- prologue ----------------
    if (tid == 0) mbar_init(mbarL, 32);     // 32 remote arrivals per phase
    for (int i = tid; i < 200; i += NTH) {
        int c = i / 25, t = i - c * 25;
        wqT[t * 8 + c] = q_w[i];
        wwT[t * 8 + c] = w[i];
    }
    if (tid < 32) { int a = tid >> 3, c = tid & 7; fcT[c * 4 + a] = fc_w[tid]; }
    if (tid >= 64 && tid < 114) {
        int t = tid - 64;
        float s = 0.f;
        #pragma unroll 5
        for (int c = 0; c < 150; ++c) s += r_w[c] * encode_w[c * 50 + t];
        We[t] = s;
    }
    if (tid == 63) {
        float s = 0.f;
        for (int c = 0; c < 150; ++c) s += r_w[c] * encode_b[c];
        sm[OFF_BE] = s;
    }
    for (int i = tid; i < MROWS * MP; i += NTH) msm[i] = 3;  // sentinel
    for (int i = tid; i < OFF_M; i += NTH) sm[i] = 0.f;      // VA, VB, R planes
    __syncthreads();

    if (tid < 75) {
        int t = tid / 3, mv = tid - t * 3;
        Lt[t * 4 + mv] = We[t] * emb[2 * mv] + We[25 + t] * emb[2 * mv + 1];
        if (mv == 0) Lt[t * 4 + 3] = 0.f;
    }
    const int* mz = maze + b * 4096;
    for (int i = tid; i < MROWS * 64; i += NTH) {
        int mr = i >> 6, c = i & 63, g = gy0 - 4 + mr;
        if ((unsigned)g < 64u) msm[mr * MP + c + 2] = mz[g * 64 + c];
    }
    CSYNC();   // cluster-wide: mbar init + zeroed planes visible to peer

    // ---------------- r = LUT-conv(maze) + b_eff ----------------
    {
        const float bv = sm[OFF_BE];
        for (int i = tid; i < 36 * 64; i += NTH) {
            int vr = i >> 6, c = i & 63, g = gy0 - 2 + vr;
            if ((unsigned)g < 64u) {
                float s = bv;
                #pragma unroll
                for (int dy = 0; dy < 5; dy++)
                    #pragma unroll
                    for (int dx = 0; dx < 5; dx++)
                        s += Lt[(dy * 5 + dx) * 4 + msm[(vr + dy) * MP + c + dx]];
                rF[vr * VP + c + 2] = s;
            }
        }
    }
    __syncthreads();

    // ---------------- qr = conv(r, wq) -> registers; v0 = max_c qr ----------------
    ull qr2[4][2][2];
    uint32_t ph = 0;
    {
        ull qc2[4][2][2];
        #pragma unroll
        for (int cp = 0; cp < 4; cp++)
            #pragma unroll
            for (int i = 0; i < 2; i++) { qc2[cp][i][0] = 0ull; qc2[cp][i][1] = 0ull; }
        const float* wT = wqT;
        CONV_PAIRS(rF);
        #pragma unroll
        for (int cp = 0; cp < 4; cp++)
            #pragma unroll
            for (int i = 0; i < 2; i++) {
                qr2[cp][i][0] = qc2[cp][i][0];
                qr2[cp][i][1] = qc2[cp][i][1];
            }
        float vn[2][2];
        #pragma unroll
        for (int i = 0; i < 2; i++)
            #pragma unroll
            for (int j = 0; j < 2; j++) {
                float lo, hi;
                UNPK2(lo, hi, qc2[0][i][j]);
                float m = fmaxf(lo, hi);
                #pragma unroll
                for (int cp = 1; cp < 4; cp++) {
                    UNPK2(lo, hi, qc2[cp][i][j]);
                    m = fmaxf(m, fmaxf(lo, hi));
                }
                vn[i][j] = m;
            }
        #pragma unroll
        for (int i = 0; i < 2; i++)
            *(float2*)(vaF + (yo + 2 + i) * VP + x0 + 2) = make_float2(vn[i][0], vn[i][1]);
        if (bwarp) {
            #pragma unroll
            for (int i = 0; i < 2; i++)
                st_remote_f2(peer32 + (OFF_VA + (prow0 + i) * VP + x0 + 2) * 4,
                             vn[i][0], vn[i][1]);
            mbar_arrive_remote(mbarR);   // completes peer's phase 0
        }
    }
    __syncthreads();

    // ---------------- 9 value-iteration steps ----------------
    for (int k = 0; k < 9; ++k) {
        const float* vin  = (k & 1) ? vbF : vaF;
        float*       vout = (k & 1) ? vaF : vbF;
        const int    outOff = (k & 1) ? OFF_VA : OFF_VB;
        if (bwarp) { mbar_wait(mbarL, ph); ph ^= 1; }   // halo of vin ready
        ull qc2[4][2][2];
        #pragma unroll
        for (int cp = 0; cp < 4; cp++)
            #pragma unroll
            for (int i = 0; i < 2; i++) {
                qc2[cp][i][0] = qr2[cp][i][0];
                qc2[cp][i][1] = qr2[cp][i][1];
            }
        const float* wT = wwT;
        CONV_PAIRS(vin);
        float vn[2][2];
        #pragma unroll
        for (int i = 0; i < 2; i++)
            #pragma unroll
            for (int j = 0; j < 2; j++) {
                float lo, hi;
                UNPK2(lo, hi, qc2[0][i][j]);
                float m = fmaxf(lo, hi);
                #pragma unroll
                for (int cp = 1; cp < 4; cp++) {
                    UNPK2(lo, hi, qc2[cp][i][j]);
                    m = fmaxf(m, fmaxf(lo, hi));
                }
                vn[i][j] = m;
            }
        #pragma unroll
        for (int i = 0; i < 2; i++)
            *(float2*)(vout + (yo + 2 + i) * VP + x0 + 2) = make_float2(vn[i][0], vn[i][1]);
        if (bwarp) {
            #pragma unroll
            for (int i = 0; i < 2; i++)
                st_remote_f2(peer32 + (outOff + (prow0 + i) * VP + x0 + 2) * 4,
                             vn[i][0], vn[i][1]);
            mbar_arrive_remote(mbarR);   // completes peer's phase k+1
        }
        __syncthreads();
    }

    // ---------------- final: q10 = qr + conv(v9,w); out = q10 @ fc^T ----------------
    {
        const float* vin = vbF;          // v9 in plane B (k=8 wrote VB)
        if (bwarp) mbar_wait(mbarL, ph); // phase 9: halo of v9 ready
        ull qc2[4][2][2];
        #pragma unroll
        for (int cp = 0; cp < 4; cp++)
            #pragma unroll
            for (int i = 0; i < 2; i++) {
                qc2[cp][i][0] = qr2[cp][i][0];
                qc2[cp][i][1] = qr2[cp][i][1];
            }
        const float* wT = wwT;
        CONV_PAIRS(vin);
        float* og = out + (size_t)b * 4096 * 4;
        #pragma unroll
        for (int i = 0; i < 2; i++)
            #pragma unroll
            for (int j = 0; j < 2; j++) {
                float q[8];
                #pragma unroll
                for (int cp = 0; cp < 4; cp++)
                    UNPK2(q[2 * cp], q[2 * cp + 1], qc2[cp][i][j]);
                float4 o = make_float4(0.f, 0.f, 0.f, 0.f);
                #pragma unroll
                for (int c = 0; c < 8; c++) {
                    float4 fr = *(const float4*)(fcT + c * 4);
                    o.x += q[c] * fr.x;
                    o.y += q[c] * fr.y;
                    o.z += q[c] * fr.z;
                    o.w += q[c] * fr.w;
                }
                *(float4*)(og + ((gy0 + yo + i) * 64 + x0 + j) * 4) = o;
            }
    }
}

extern "C" void kernel_launch(void* const* d_in, const int* in_sizes, int n_in,
                              void* d_out, int out_size) {
    cudaFuncSetAttribute(vin_kernel, cudaFuncAttributeMaxDynamicSharedMemorySize,
                         SMEM_BYTES);
    const int B = in_sizes[0] >> 12;   // maze elements / 4096
    dim3 grid(2, B, 1);
    vin_kernel<<<grid, NTH, SMEM_BYTES>>>(
        (const int*)  d_in[0],  // maze
        (const float*)d_in[1],  // emb
        (const float*)d_in[2],  // encode_w
        (const float*)d_in[3],  // encode_b
        (const float*)d_in[4],  // r_w
        (const float*)d_in[5],  // q_w
        (const float*)d_in[6],  // w
        (const float*)d_in[7],  // fc_w
        (float*)d_out);
}